// round 12
// baseline (speedup 1.0000x reference)
#include <cuda_runtime.h>
#include <cuda_fp16.h>
#include <mma.h>
#include <math.h>
#include <stdint.h>

using namespace nvcuda;

#define N_TOK  16384
#define DMODEL 512
#define BATCH  8
#define NHEAD  8
#define HDIM   64
#define NLAYER 6
#define D3     1536

// ---------------------------------------------------------------------------
// Scratch
// ---------------------------------------------------------------------------
__device__ int   g_offsets[BATCH + 1];
__device__ __align__(256) float  g_xin  [N_TOK * DMODEL];
__device__ __align__(256) float  g_x    [N_TOK * DMODEL];
__device__ __align__(256) float  g_tmp  [N_TOK * DMODEL];
__device__ __align__(256) __half g_wtin [DMODEL * DMODEL];
__device__ __align__(256) __half g_wtout[DMODEL * DMODEL];
__device__ __align__(256) __half g_xr   [N_TOK * DMODEL];
__device__ __align__(256) __half g_featr[N_TOK * DMODEL];
__device__ __align__(256) __half g_qkv  [N_TOK * D3];
__device__ __align__(256) __half g_attn [N_TOK * DMODEL];
__device__ __align__(256) __half g_h1   [N_TOK * DMODEL];
__device__ __align__(256) __half g_inw_h[NLAYER * D3 * DMODEL];
__device__ __align__(256) __half g_ow_h [NLAYER * DMODEL * DMODEL];
__device__ __align__(256) __half g_w1_h [NLAYER * DMODEL * DMODEL];
__device__ __align__(256) __half g_w2_h [NLAYER * DMODEL * DMODEL];

// ---------------------------------------------------------------------------
// helpers
// ---------------------------------------------------------------------------
__device__ __forceinline__ uint32_t s2u(const void* p)
{
    return (uint32_t)__cvta_generic_to_shared(p);
}
__device__ __forceinline__ void cp16(uint32_t dst, const void* src)
{
    asm volatile("cp.async.cg.shared.global [%0], [%1], 16;" :: "r"(dst), "l"(src));
}
__device__ __forceinline__ void cp_commit()
{
    asm volatile("cp.async.commit_group;" ::: "memory");
}
template <int N>
__device__ __forceinline__ void cp_wait()
{
    asm volatile("cp.async.wait_group %0;" :: "n"(N) : "memory");
}
__device__ __forceinline__ uint2 f4_to_h4(float4 v)
{
    __half2 lo = __floats2half2_rn(v.x, v.y);
    __half2 hi = __floats2half2_rn(v.z, v.w);
    uint2 r;
    r.x = *(uint32_t*)&lo;
    r.y = *(uint32_t*)&hi;
    return r;
}

// ---------------------------------------------------------------------------
// Prologue 1: segment offsets
// ---------------------------------------------------------------------------
__global__ void seg_kernel(const int* __restrict__ batch_idx, int n)
{
    __shared__ int cnt[BATCH];
    if (threadIdx.x < BATCH) cnt[threadIdx.x] = 0;
    __syncthreads();
    for (int i = threadIdx.x; i < n; i += blockDim.x)
        atomicAdd(&cnt[batch_idx[i]], 1);
    __syncthreads();
    if (threadIdx.x == 0) {
        int s = 0;
        for (int b = 0; b < BATCH; b++) { g_offsets[b] = s; s += cnt[b]; }
        g_offsets[BATCH] = s;
    }
}

__device__ __forceinline__ void cvt4(const float* __restrict__ in,
                                     __half* __restrict__ out, int i)
{
    ((uint2*)out)[i] = f4_to_h4(((const float4*)in)[i]);
}

// ---------------------------------------------------------------------------
// Prologue 2: transpose+cvt w_in/w_out, cvt features + in_proj_w
// ---------------------------------------------------------------------------
#define FEAT4 (N_TOK * DMODEL / 4)
#define INW4  (NLAYER * D3 * DMODEL / 4)

__global__ void prologueA(const float* __restrict__ w_in,
                          const float* __restrict__ w_out,
                          const float* __restrict__ features,
                          const float* __restrict__ in_proj_w)
{
    const int bid = blockIdx.x;
    const int t   = threadIdx.x;
    if (bid < 512) {
        __shared__ float tile[32][33];
        const float* src = (bid < 256) ? w_in   : w_out;
        __half*      dst = (bid < 256) ? g_wtin : g_wtout;
        int tl = bid & 255;
        int bx = (tl & 15) * 32, by = (tl >> 4) * 32;
        int x = t & 31, y = t >> 5;
        #pragma unroll
        for (int i = 0; i < 32; i += 8)
            tile[y + i][x] = src[(size_t)(by + y + i) * 512 + bx + x];
        __syncthreads();
        #pragma unroll
        for (int i = 0; i < 32; i += 8)
            dst[(size_t)(bx + y + i) * 512 + by + x] = __float2half_rn(tile[x][y + i]);
    } else {
        const int total = FEAT4 + INW4;
        for (int i = (bid - 512) * 256 + t; i < total; i += 1024 * 256) {
            if (i < FEAT4) cvt4(features, g_featr, i);
            else           cvt4(in_proj_w, g_inw_h, i - FEAT4);
        }
    }
}

// ---------------------------------------------------------------------------
// Prologue 3: cvt out_proj_w / lin1_w / lin2_w
// ---------------------------------------------------------------------------
#define W4 (NLAYER * DMODEL * DMODEL / 4)

__global__ void prologueB(const float* __restrict__ ow,
                          const float* __restrict__ w1,
                          const float* __restrict__ w2)
{
    const int total = 3 * W4;
    for (int i = blockIdx.x * blockDim.x + threadIdx.x; i < total;
         i += gridDim.x * blockDim.x) {
        if (i < W4)          cvt4(ow, g_ow_h, i);
        else if (i < 2 * W4) cvt4(w1, g_w1_h, i - W4);
        else                 cvt4(w2, g_w2_h, i - 2 * W4);
    }
}

// out = half(a + b)
__global__ void addcvt_kernel(const float* __restrict__ a, const float* __restrict__ b,
                              __half* __restrict__ out, int n4)
{
    int i = blockIdx.x * blockDim.x + threadIdx.x;
    for (; i < n4; i += gridDim.x * blockDim.x) {
        float4 va = ((const float4*)a)[i];
        float4 vb = ((const float4*)b)[i];
        va.x += vb.x; va.y += vb.y; va.z += vb.z; va.w += vb.w;
        ((uint2*)out)[i] = f4_to_h4(va);
    }
}

// ---------------------------------------------------------------------------
// fp16 NT GEMM v6, fp32 accumulate:  C = A @ W^T + bias
// Tile 128x128, k-tile 64, 3-stage cp.async ring (prefetch distance 2, one
// barrier per k-tile), and CUTLASS-style REGISTER FRAGMENT DOUBLE BUFFERING:
// a/b fragments for step kk+16 are loaded while the mma for kk executes,
// hiding the LDSM->HMMA RAW latency inside each warp. ~180 regs -> 1 CTA/SM.
// 256 threads (8 warps, warp tile 32x64). EPI 1 = SiLU.
// Smem: 3 x 36864 B = 110592 B; epilogue reuses as Cs float[128][132].
// ---------------------------------------------------------------------------
#define G6_MAT_H   (128 * 72)
#define G6_STAGE_H (2 * G6_MAT_H)
#define G6_SMEM    (3 * G6_STAGE_H * 2)    // 110592 bytes

template <int EPI>
__global__ __launch_bounds__(256, 1)
void gemm6_kernel(const __half* __restrict__ A, const __half* __restrict__ W,
                  const float* __restrict__ bias,
                  float* __restrict__ C, __half* __restrict__ Cr,
                  int M, int Nout, int K)
{
    extern __shared__ __align__(1024) char smc[];
    __half* hs = (__half*)smc;

    const int m0 = blockIdx.y * 128;
    const int n0 = blockIdx.x * 128;
    const int t  = threadIdx.x;
    const int wid = t >> 5;
    const int wm = wid & 3;        // M: 4 warps x 32 rows
    const int wn = wid >> 2;       // N: 2 warps x 64 cols

    wmma::fragment<wmma::accumulator, 16, 16, 16, float> acc[2][4];
    #pragma unroll
    for (int i = 0; i < 2; i++)
        #pragma unroll
        for (int j = 0; j < 4; j++)
            wmma::fill_fragment(acc[i][j], 0.f);

    const int row = t >> 1;            // 0..127
    const int cb  = t & 1;             // half-row (32 halfs = 64B)
    const __half* aB = A + (size_t)(m0 + row) * K;
    const __half* wB = W + (size_t)(n0 + row) * K;

    auto issue = [&](int k0, int s) {
        uint32_t da = s2u(hs + s * G6_STAGE_H + row * 72 + cb * 32);
        uint32_t dw = da + G6_MAT_H * 2;   // bytes
        const __half* sa = aB + k0 + cb * 32;
        const __half* sw = wB + k0 + cb * 32;
        #pragma unroll
        for (int u = 0; u < 4; u++) {
            cp16(da + u * 16, sa + u * 8);
            cp16(dw + u * 16, sw + u * 8);
        }
        cp_commit();
    };

    const int NT = K >> 6;             // K=512 -> 8
    issue(0, 0);
    if (NT > 1) issue(64, 1); else cp_commit();

    // register fragment double buffers
    wmma::fragment<wmma::matrix_a, 16, 16, 16, __half, wmma::row_major> afr[2][2];
    wmma::fragment<wmma::matrix_b, 16, 16, 16, __half, wmma::col_major> bfr[2][4];

    for (int kt = 0; kt < NT; kt++) {
        cp_wait<1>();                  // tile kt resident (kt+1 may be in flight)
        __syncthreads();               // visibility + orders reads of issue target
        if (kt + 2 < NT) issue((kt + 2) * 64, (kt + 2) % 3);
        else             cp_commit();

        const __half* As = hs + (kt % 3) * G6_STAGE_H;
        const __half* Ws = As + G6_MAT_H;

        // preload fragments for kk = 0 into buffer 0
        #pragma unroll
        for (int j = 0; j < 4; j++)
            wmma::load_matrix_sync(bfr[0][j], Ws + (wn * 64 + j * 16) * 72, 72);
        #pragma unroll
        for (int i = 0; i < 2; i++)
            wmma::load_matrix_sync(afr[0][i], As + (wm * 32 + i * 16) * 72, 72);

        #pragma unroll
        for (int kx = 0; kx < 4; kx++) {
            const int cur = kx & 1;
            const int nxt = cur ^ 1;
            if (kx < 3) {
                const int kk2 = (kx + 1) * 16;
                #pragma unroll
                for (int j = 0; j < 4; j++)
                    wmma::load_matrix_sync(bfr[nxt][j],
                                           Ws + (wn * 64 + j * 16) * 72 + kk2, 72);
                #pragma unroll
                for (int i = 0; i < 2; i++)
                    wmma::load_matrix_sync(afr[nxt][i],
                                           As + (wm * 32 + i * 16) * 72 + kk2, 72);
            }
            #pragma unroll
            for (int i = 0; i < 2; i++)
                #pragma unroll
                for (int j = 0; j < 4; j++)
                    wmma::mma_sync(acc[i][j], afr[cur][i], bfr[cur][j], acc[i][j]);
        }
    }

    // Epilogue through smem (reuse as float Cs[128][132])
    __syncthreads();                   // all compute done before overwriting smem
    float* Cs = (float*)smc;
    #pragma unroll
    for (int i = 0; i < 2; i++)
        #pragma unroll
        for (int j = 0; j < 4; j++)
            wmma::store_matrix_sync(Cs + (wm * 32 + i * 16) * 132 + wn * 64 + j * 16,
                                    acc[i][j], 132, wmma::mem_row_major);
    __syncthreads();

    const int r2  = t >> 1;
    const int cb2 = (t & 1) * 64;
    #pragma unroll
    for (int u = 0; u < 16; u++) {
        int c = cb2 + u * 4;
        float4 v = *(const float4*)&Cs[r2 * 132 + c];
        if (bias) {
            float4 bv = *(const float4*)(bias + n0 + c);
            v.x += bv.x; v.y += bv.y; v.z += bv.z; v.w += bv.w;
        }
        if (EPI == 1) {
            v.x = v.x / (1.f + __expf(-v.x));
            v.y = v.y / (1.f + __expf(-v.y));
            v.z = v.z / (1.f + __expf(-v.z));
            v.w = v.w / (1.f + __expf(-v.w));
        }
        size_t idx = (size_t)(m0 + r2) * Nout + n0 + c;
        if (C)  *(float4*)(C + idx) = v;
        if (Cr) *(uint2*)(Cr + idx) = f4_to_h4(v);
    }
}

// ---------------------------------------------------------------------------
// Residual + LayerNorm, warp-per-row (no block barriers), dual write.
// ---------------------------------------------------------------------------
__global__ __launch_bounds__(256)
void ln_kernel(float* __restrict__ x, const float* __restrict__ r,
               const float* __restrict__ g, const float* __restrict__ b,
               __half* __restrict__ xr)
{
    const int row  = blockIdx.x * 8 + (threadIdx.x >> 5);
    const int lane = threadIdx.x & 31;
    const size_t base = (size_t)row * 512;

    float4 v[4];
    float s = 0.f, sq = 0.f;
    #pragma unroll
    for (int u = 0; u < 4; u++) {
        float4 a = *(const float4*)(x + base + u * 128 + lane * 4);
        float4 c = *(const float4*)(r + base + u * 128 + lane * 4);
        a.x += c.x; a.y += c.y; a.z += c.z; a.w += c.w;
        v[u] = a;
        s  += (a.x + a.y) + (a.z + a.w);
        sq += (a.x * a.x + a.y * a.y) + (a.z * a.z + a.w * a.w);
    }
    #pragma unroll
    for (int m = 16; m >= 1; m >>= 1) {
        s  += __shfl_xor_sync(0xffffffffu, s,  m);
        sq += __shfl_xor_sync(0xffffffffu, sq, m);
    }
    const float mean = s * (1.f / 512.f);
    const float var  = sq * (1.f / 512.f) - mean * mean;
    const float inv  = rsqrtf(var + 1e-5f);

    #pragma unroll
    for (int u = 0; u < 4; u++) {
        float4 gv = *(const float4*)(g + u * 128 + lane * 4);
        float4 bb = *(const float4*)(b + u * 128 + lane * 4);
        float4 a = v[u];
        a.x = (a.x - mean) * inv * gv.x + bb.x;
        a.y = (a.y - mean) * inv * gv.y + bb.y;
        a.z = (a.z - mean) * inv * gv.z + bb.z;
        a.w = (a.w - mean) * inv * gv.w + bb.w;
        *(float4*)(x + base + u * 128 + lane * 4) = a;
        ((uint2*)xr)[(base + u * 128 + lane * 4) >> 2] = f4_to_h4(a);
    }
}

// ---------------------------------------------------------------------------
// Flash attention v5 (validated round 11): fp16 operands, fp32 accum/softmax,
// 2 CTA/SM, grid-stride over q-tiles, ONE block barrier per kv tile.
// ---------------------------------------------------------------------------
#define AR 72
#define ATT3_SMEM 110592
#define ATT_GRIDX 24

__global__ __launch_bounds__(256, 2)
void attn3_kernel(const __half* __restrict__ qkv, __half* __restrict__ out)
{
    extern __shared__ __align__(1024) char smc[];
    __half* Qs    = (__half*)smc;                 // [128][72]
    __half* Ks[2] = { Qs + 128 * AR,          Qs + 128 * AR + 64 * AR };
    __half* Vs[2] = { Qs + 128 * AR + 128 * AR, Qs + 128 * AR + 192 * AR };
    __half* Ph    = Qs + 128 * AR + 256 * AR;     // [128][72]
    float*  Sf    = (float*)(smc + 73728);        // [128][72]

    const int b   = blockIdx.z;
    const int h   = blockIdx.y;
    const int off = g_offsets[b];
    const int L   = g_offsets[b + 1] - off;

    const int t    = threadIdx.x;
    const int wid  = t >> 5;
    const int lane = t & 31;

    const __half* qbase = qkv + (size_t)off * D3 + h * HDIM;
    const __half* kbase = qbase + DMODEL;
    const __half* vbase = qbase + 2 * DMODEL;

    const int kvrow = t >> 2;
    const int kvcb  = (t & 3) * 16;
    auto issueKV = [&](int j0, int s) {
        int gj = min(j0 + kvrow, L - 1);
        const __half* kp = kbase + (size_t)gj * D3 + kvcb;
        const __half* vp = vbase + (size_t)gj * D3 + kvcb;
        uint32_t dk = s2u(Ks[s] + kvrow * AR + kvcb);
        uint32_t dv = s2u(Vs[s] + kvrow * AR + kvcb);
        #pragma unroll
        for (int u = 0; u < 2; u++) {
            cp16(dk + u * 16, kp + u * 8);
            cp16(dv + u * 16, vp + u * 8);
        }
    };

    const int srow = wid * 16 + (lane >> 1);
    const int scb  = (lane & 1) * 32;
    const float* Sw = Sf + srow * AR + scb;
    __half*      Pw = Ph + srow * AR + scb;
    const int nt = (L + 63) >> 6;

    for (int qi0 = blockIdx.x * 128; qi0 < L; qi0 += ATT_GRIDX * 128) {
        __syncthreads();   // protect Qs/Ks/Vs reuse across q-tiles

        {
            const int qrow = t >> 1;
            const int qcb  = (t & 1) * 32;
            int gi = min(qi0 + qrow, L - 1);
            const __half* qp = qbase + (size_t)gi * D3 + qcb;
            uint32_t dst = s2u(Qs + qrow * AR + qcb);
            #pragma unroll
            for (int u = 0; u < 4; u++) cp16(dst + u * 16, qp + u * 8);
        }
        issueKV(0, 0);
        cp_commit();       // group: Q + KV0

        wmma::fragment<wmma::accumulator, 16, 16, 16, float> oacc[4];
        #pragma unroll
        for (int n = 0; n < 4; n++) wmma::fill_fragment(oacc[n], 0.f);
        float lsum = 0.f;

        for (int j = 0; j < nt; j++) {
            const int s = j & 1;
            cp_wait<0>();
            __syncthreads();           // orders iter j-1's reads of s^1
            if (j + 1 < nt) { issueKV((j + 1) * 64, s ^ 1); cp_commit(); }

            wmma::fragment<wmma::accumulator, 16, 16, 16, float> sfrag[4];
            #pragma unroll
            for (int n = 0; n < 4; n++) wmma::fill_fragment(sfrag[n], 0.f);
            #pragma unroll
            for (int kk = 0; kk < 64; kk += 16) {
                wmma::fragment<wmma::matrix_a, 16, 16, 16, __half, wmma::row_major> a;
                wmma::load_matrix_sync(a, Qs + (wid * 16) * AR + kk, AR);
                #pragma unroll
                for (int n = 0; n < 4; n++) {
                    wmma::fragment<wmma::matrix_b, 16, 16, 16, __half, wmma::col_major> bf;
                    wmma::load_matrix_sync(bf, Ks[s] + (n * 16) * AR + kk, AR);
                    wmma::mma_sync(sfrag[n], a, bf, sfrag[n]);
                }
            }
            #pragma unroll
            for (int n = 0; n < 4; n++)
                wmma::store_matrix_sync(Sf + (wid * 16) * AR + n * 16,
                                        sfrag[n], AR, wmma::mem_row_major);
            __syncwarp();

            {
                const int j0 = j * 64;
                float part = 0.f;
                #pragma unroll
                for (int u = 0; u < 8; u++) {
                    float4 v = *(const float4*)(Sw + u * 4);
                    int c = j0 + scb + u * 4;
                    float p0 = (c + 0 < L) ? __expf(v.x * 0.125f) : 0.f;
                    float p1 = (c + 1 < L) ? __expf(v.y * 0.125f) : 0.f;
                    float p2 = (c + 2 < L) ? __expf(v.z * 0.125f) : 0.f;
                    float p3 = (c + 3 < L) ? __expf(v.w * 0.125f) : 0.f;
                    part += (p0 + p1) + (p2 + p3);
                    v.x = p0; v.y = p1; v.z = p2; v.w = p3;
                    *(uint2*)(Pw + u * 4) = f4_to_h4(v);
                }
                lsum += part;
            }
            __syncwarp();

            #pragma unroll
            for (int kk = 0; kk < 64; kk += 16) {
                wmma::fragment<wmma::matrix_a, 16, 16, 16, __half, wmma::row_major> a;
                wmma::load_matrix_sync(a, Ph + (wid * 16) * AR + kk, AR);
                #pragma unroll
                for (int n = 0; n < 4; n++) {
                    wmma::fragment<wmma::matrix_b, 16, 16, 16, __half, wmma::row_major> vf;
                    wmma::load_matrix_sync(vf, Vs[s] + kk * AR + n * 16, AR);
                    wmma::mma_sync(oacc[n], a, vf, oacc[n]);
                }
            }
        }

        #pragma unroll
        for (int n = 0; n < 4; n++)
            wmma::store_matrix_sync(Sf + (wid * 16) * AR + n * 16,
                                    oacc[n], AR, wmma::mem_row_major);
        __syncwarp();

        {
            float full = lsum + __shfl_xor_sync(0xffffffffu, lsum, 1);
            float inv  = 1.f / full;
            int gi = qi0 + srow;
            if (gi < L) {
                __half* op = out + (size_t)(off + gi) * DMODEL + h * HDIM + scb;
                #pragma unroll
                for (int u = 0; u < 8; u++) {
                    float4 v = *(const float4*)(Sw + u * 4);
                    v.x *= inv; v.y *= inv; v.z *= inv; v.w *= inv;
                    *(uint2*)(op + u * 4) = f4_to_h4(v);
                }
            }
        }
        __syncwarp();
    }
}

// ---------------------------------------------------------------------------
// Launch
// ---------------------------------------------------------------------------
extern "C" void kernel_launch(void* const* d_in, const int* in_sizes, int n_in,
                              void* d_out, int out_size)
{
    const float* features   = (const float*)d_in[0];
    const int*   batch_idx  = (const int*)  d_in[1];
    const float* w_in       = (const float*)d_in[2];
    const float* w_out      = (const float*)d_in[3];
    const float* in_proj_w  = (const float*)d_in[4];
    const float* in_proj_b  = (const float*)d_in[5];
    const float* out_proj_w = (const float*)d_in[6];
    const float* out_proj_b = (const float*)d_in[7];
    const float* ln1_g      = (const float*)d_in[8];
    const float* ln1_b      = (const float*)d_in[9];
    const float* lin1_w     = (const float*)d_in[10];
    const float* lin1_b     = (const float*)d_in[11];
    const float* lin2_w     = (const float*)d_in[12];
    const float* lin2_b     = (const float*)d_in[13];
    const float* ln2_g      = (const float*)d_in[14];
    const float* ln2_b      = (const float*)d_in[15];
    (void)in_sizes; (void)n_in;

    float *xin, *x, *tmp;
    __half *xr, *featr, *qkv, *attn, *h1, *wtin, *wtout, *inw_h, *ow_h, *w1_h, *w2_h;
    cudaGetSymbolAddress((void**)&xin,   g_xin);
    cudaGetSymbolAddress((void**)&x,     g_x);
    cudaGetSymbolAddress((void**)&tmp,   g_tmp);
    cudaGetSymbolAddress((void**)&xr,    g_xr);
    cudaGetSymbolAddress((void**)&featr, g_featr);
    cudaGetSymbolAddress((void**)&qkv,   g_qkv);
    cudaGetSymbolAddress((void**)&attn,  g_attn);
    cudaGetSymbolAddress((void**)&h1,    g_h1);
    cudaGetSymbolAddress((void**)&wtin,  g_wtin);
    cudaGetSymbolAddress((void**)&wtout, g_wtout);
    cudaGetSymbolAddress((void**)&inw_h, g_inw_h);
    cudaGetSymbolAddress((void**)&ow_h,  g_ow_h);
    cudaGetSymbolAddress((void**)&w1_h,  g_w1_h);
    cudaGetSymbolAddress((void**)&w2_h,  g_w2_h);

    cudaFuncSetAttribute(attn3_kernel,
                         cudaFuncAttributeMaxDynamicSharedMemorySize, ATT3_SMEM);
    cudaFuncSetAttribute(gemm6_kernel<0>,
                         cudaFuncAttributeMaxDynamicSharedMemorySize, G6_SMEM);
    cudaFuncSetAttribute(gemm6_kernel<1>,
                         cudaFuncAttributeMaxDynamicSharedMemorySize, G6_SMEM);

    seg_kernel<<<1, 256>>>(batch_idx, N_TOK);
    prologueA<<<1536, 256>>>(w_in, w_out, features, in_proj_w);
    prologueB<<<1024, 256>>>(out_proj_w, lin1_w, lin2_w);

    const dim3 g512 (DMODEL / 128, N_TOK / 128);
    const dim3 g1536(D3 / 128,     N_TOK / 128);
    const dim3 gatt (ATT_GRIDX, NHEAD, BATCH);

    // x_in = features @ w_in   (fp32 -> xin, fp16 -> xr)
    gemm6_kernel<0><<<g512, 256, G6_SMEM>>>(featr, wtin, nullptr,
                                            xin, xr, N_TOK, DMODEL, DMODEL);
    cudaMemcpyAsync(x, xin, (size_t)N_TOK * DMODEL * sizeof(float),
                    cudaMemcpyDeviceToDevice);

    for (int l = 0; l < NLAYER; l++) {
        const __half* inw = inw_h      + (size_t)l * D3 * DMODEL;
        const float*  inb = in_proj_b  + (size_t)l * D3;
        const __half* ow  = ow_h       + (size_t)l * DMODEL * DMODEL;
        const float*  ob  = out_proj_b + (size_t)l * DMODEL;
        const __half* w1  = w1_h       + (size_t)l * DMODEL * DMODEL;
        const float*  b1  = lin1_b     + (size_t)l * DMODEL;
        const __half* w2  = w2_h       + (size_t)l * DMODEL * DMODEL;
        const float*  b2  = lin2_b     + (size_t)l * DMODEL;

        gemm6_kernel<0><<<g1536, 256, G6_SMEM>>>(xr, inw, inb,
                                                 nullptr, qkv, N_TOK, D3, DMODEL);
        attn3_kernel<<<gatt, 256, ATT3_SMEM>>>(qkv, attn);
        gemm6_kernel<0><<<g512, 256, G6_SMEM>>>(attn, ow, ob,
                                                tmp, nullptr, N_TOK, DMODEL, DMODEL);
        ln_kernel<<<N_TOK / 8, 256>>>(x, tmp, ln1_g + l * DMODEL, ln1_b + l * DMODEL, xr);
        gemm6_kernel<1><<<g512, 256, G6_SMEM>>>(xr, w1, b1,
                                                nullptr, h1, N_TOK, DMODEL, DMODEL);
        gemm6_kernel<0><<<g512, 256, G6_SMEM>>>(h1, w2, b2,
                                                tmp, nullptr, N_TOK, DMODEL, DMODEL);
        ln_kernel<<<N_TOK / 8, 256>>>(x, tmp, ln2_g + l * DMODEL, ln2_b + l * DMODEL, xr);
    }

    // out = (x + x_in) @ w_out
    addcvt_kernel<<<512, 256>>>(x, xin, featr, N_TOK * DMODEL / 4);
    gemm6_kernel<0><<<g512, 256, G6_SMEM>>>(featr, wtout, nullptr,
                                            (float*)d_out, nullptr,
                                            N_TOK, DMODEL, DMODEL);
}

// round 13
// speedup vs baseline: 1.0646x; 1.0646x over previous
#include <cuda_runtime.h>
#include <cuda_fp16.h>
#include <mma.h>
#include <math.h>
#include <stdint.h>

using namespace nvcuda;

#define N_TOK  16384
#define DMODEL 512
#define BATCH  8
#define NHEAD  8
#define HDIM   64
#define NLAYER 6
#define D3     1536

// ---------------------------------------------------------------------------
// Scratch
// ---------------------------------------------------------------------------
__device__ int   g_offsets[BATCH + 1];
__device__ __align__(256) float  g_xin  [N_TOK * DMODEL];
__device__ __align__(256) float  g_x    [N_TOK * DMODEL];
__device__ __align__(256) float  g_tmp  [N_TOK * DMODEL];
__device__ __align__(256) __half g_wtin [DMODEL * DMODEL];
__device__ __align__(256) __half g_wtout[DMODEL * DMODEL];
__device__ __align__(256) __half g_xr   [N_TOK * DMODEL];
__device__ __align__(256) __half g_featr[N_TOK * DMODEL];
__device__ __align__(256) __half g_qkv  [N_TOK * D3];
__device__ __align__(256) __half g_attn [N_TOK * DMODEL];
__device__ __align__(256) __half g_h1   [N_TOK * DMODEL];
__device__ __align__(256) __half g_inw_h[NLAYER * D3 * DMODEL];
__device__ __align__(256) __half g_ow_h [NLAYER * DMODEL * DMODEL];
__device__ __align__(256) __half g_w1_h [NLAYER * DMODEL * DMODEL];
__device__ __align__(256) __half g_w2_h [NLAYER * DMODEL * DMODEL];

// ---------------------------------------------------------------------------
// helpers
// ---------------------------------------------------------------------------
__device__ __forceinline__ uint32_t s2u(const void* p)
{
    return (uint32_t)__cvta_generic_to_shared(p);
}
__device__ __forceinline__ void cp16(uint32_t dst, const void* src)
{
    asm volatile("cp.async.cg.shared.global [%0], [%1], 16;" :: "r"(dst), "l"(src));
}
__device__ __forceinline__ void cp_commit()
{
    asm volatile("cp.async.commit_group;" ::: "memory");
}
template <int N>
__device__ __forceinline__ void cp_wait()
{
    asm volatile("cp.async.wait_group %0;" :: "n"(N) : "memory");
}
__device__ __forceinline__ uint2 f4_to_h4(float4 v)
{
    __half2 lo = __floats2half2_rn(v.x, v.y);
    __half2 hi = __floats2half2_rn(v.z, v.w);
    uint2 r;
    r.x = *(uint32_t*)&lo;
    r.y = *(uint32_t*)&hi;
    return r;
}

// ---------------------------------------------------------------------------
// Prologue 1: segment offsets
// ---------------------------------------------------------------------------
__global__ void seg_kernel(const int* __restrict__ batch_idx, int n)
{
    __shared__ int cnt[BATCH];
    if (threadIdx.x < BATCH) cnt[threadIdx.x] = 0;
    __syncthreads();
    for (int i = threadIdx.x; i < n; i += blockDim.x)
        atomicAdd(&cnt[batch_idx[i]], 1);
    __syncthreads();
    if (threadIdx.x == 0) {
        int s = 0;
        for (int b = 0; b < BATCH; b++) { g_offsets[b] = s; s += cnt[b]; }
        g_offsets[BATCH] = s;
    }
}

__device__ __forceinline__ void cvt4(const float* __restrict__ in,
                                     __half* __restrict__ out, int i)
{
    ((uint2*)out)[i] = f4_to_h4(((const float4*)in)[i]);
}

// ---------------------------------------------------------------------------
// Prologue 2: transpose+cvt w_in/w_out, cvt features + in_proj_w
// ---------------------------------------------------------------------------
#define FEAT4 (N_TOK * DMODEL / 4)
#define INW4  (NLAYER * D3 * DMODEL / 4)

__global__ void prologueA(const float* __restrict__ w_in,
                          const float* __restrict__ w_out,
                          const float* __restrict__ features,
                          const float* __restrict__ in_proj_w)
{
    const int bid = blockIdx.x;
    const int t   = threadIdx.x;
    if (bid < 512) {
        __shared__ float tile[32][33];
        const float* src = (bid < 256) ? w_in   : w_out;
        __half*      dst = (bid < 256) ? g_wtin : g_wtout;
        int tl = bid & 255;
        int bx = (tl & 15) * 32, by = (tl >> 4) * 32;
        int x = t & 31, y = t >> 5;
        #pragma unroll
        for (int i = 0; i < 32; i += 8)
            tile[y + i][x] = src[(size_t)(by + y + i) * 512 + bx + x];
        __syncthreads();
        #pragma unroll
        for (int i = 0; i < 32; i += 8)
            dst[(size_t)(bx + y + i) * 512 + by + x] = __float2half_rn(tile[x][y + i]);
    } else {
        const int total = FEAT4 + INW4;
        for (int i = (bid - 512) * 256 + t; i < total; i += 1024 * 256) {
            if (i < FEAT4) cvt4(features, g_featr, i);
            else           cvt4(in_proj_w, g_inw_h, i - FEAT4);
        }
    }
}

// ---------------------------------------------------------------------------
// Prologue 3: cvt out_proj_w / lin1_w / lin2_w
// ---------------------------------------------------------------------------
#define W4 (NLAYER * DMODEL * DMODEL / 4)

__global__ void prologueB(const float* __restrict__ ow,
                          const float* __restrict__ w1,
                          const float* __restrict__ w2)
{
    const int total = 3 * W4;
    for (int i = blockIdx.x * blockDim.x + threadIdx.x; i < total;
         i += gridDim.x * blockDim.x) {
        if (i < W4)          cvt4(ow, g_ow_h, i);
        else if (i < 2 * W4) cvt4(w1, g_w1_h, i - W4);
        else                 cvt4(w2, g_w2_h, i - 2 * W4);
    }
}

// out = half(a + b)
__global__ void addcvt_kernel(const float* __restrict__ a, const float* __restrict__ b,
                              __half* __restrict__ out, int n4)
{
    int i = blockIdx.x * blockDim.x + threadIdx.x;
    for (; i < n4; i += gridDim.x * blockDim.x) {
        float4 va = ((const float4*)a)[i];
        float4 vb = ((const float4*)b)[i];
        va.x += vb.x; va.y += vb.y; va.z += vb.z; va.w += vb.w;
        ((uint2*)out)[i] = f4_to_h4(va);
    }
}

// ---------------------------------------------------------------------------
// fp16 NT GEMM (round-11 validated): tile 128x128, k-tile 64, 2-stage
// cp.async ring, ONE barrier per k-tile, 2 CTA/SM. EPI 1 = SiLU.
// ---------------------------------------------------------------------------
#define G5_MAT_H   (128 * 72)
#define G5_STAGE_H (2 * G5_MAT_H)
#define G5_SMEM    (2 * G5_STAGE_H * 2)    // 73728 bytes

template <int EPI>
__global__ __launch_bounds__(256, 2)
void gemm5_kernel(const __half* __restrict__ A, const __half* __restrict__ W,
                  const float* __restrict__ bias,
                  float* __restrict__ C, __half* __restrict__ Cr,
                  int M, int Nout, int K)
{
    extern __shared__ __align__(1024) char smc[];
    __half* hs = (__half*)smc;

    const int m0 = blockIdx.y * 128;
    const int n0 = blockIdx.x * 128;
    const int t  = threadIdx.x;
    const int wid = t >> 5;
    const int wm = wid & 3;
    const int wn = wid >> 2;

    wmma::fragment<wmma::accumulator, 16, 16, 16, float> acc[2][4];
    #pragma unroll
    for (int i = 0; i < 2; i++)
        #pragma unroll
        for (int j = 0; j < 4; j++)
            wmma::fill_fragment(acc[i][j], 0.f);

    const int row = t >> 1;
    const int cb  = t & 1;
    const __half* aB = A + (size_t)(m0 + row) * K;
    const __half* wB = W + (size_t)(n0 + row) * K;

    auto issue = [&](int k0, int s) {
        uint32_t da = s2u(hs + s * G5_STAGE_H + row * 72 + cb * 32);
        uint32_t dw = da + G5_MAT_H * 2;
        const __half* sa = aB + k0 + cb * 32;
        const __half* sw = wB + k0 + cb * 32;
        #pragma unroll
        for (int u = 0; u < 4; u++) {
            cp16(da + u * 16, sa + u * 8);
            cp16(dw + u * 16, sw + u * 8);
        }
        cp_commit();
    };

    const int NT = K >> 6;
    issue(0, 0);

    for (int kt = 0; kt < NT; kt++) {
        const int s = kt & 1;
        cp_wait<0>();
        __syncthreads();
        if (kt + 1 < NT) issue((kt + 1) * 64, s ^ 1);
        const __half* As = hs + s * G5_STAGE_H;
        const __half* Ws = As + G5_MAT_H;
        #pragma unroll
        for (int kk = 0; kk < 64; kk += 16) {
            wmma::fragment<wmma::matrix_b, 16, 16, 16, __half, wmma::col_major> b[4];
            #pragma unroll
            for (int j = 0; j < 4; j++)
                wmma::load_matrix_sync(b[j], Ws + (wn * 64 + j * 16) * 72 + kk, 72);
            #pragma unroll
            for (int i = 0; i < 2; i++) {
                wmma::fragment<wmma::matrix_a, 16, 16, 16, __half, wmma::row_major> a;
                wmma::load_matrix_sync(a, As + (wm * 32 + i * 16) * 72 + kk, 72);
                #pragma unroll
                for (int j = 0; j < 4; j++)
                    wmma::mma_sync(acc[i][j], a, b[j], acc[i][j]);
            }
        }
    }

    __syncthreads();
    float* Cs = (float*)smc;
    #pragma unroll
    for (int i = 0; i < 2; i++)
        #pragma unroll
        for (int j = 0; j < 4; j++)
            wmma::store_matrix_sync(Cs + (wm * 32 + i * 16) * 132 + wn * 64 + j * 16,
                                    acc[i][j], 132, wmma::mem_row_major);
    __syncthreads();

    const int r2  = t >> 1;
    const int cb2 = (t & 1) * 64;
    #pragma unroll
    for (int u = 0; u < 16; u++) {
        int c = cb2 + u * 4;
        float4 v = *(const float4*)&Cs[r2 * 132 + c];
        if (bias) {
            float4 bv = *(const float4*)(bias + n0 + c);
            v.x += bv.x; v.y += bv.y; v.z += bv.z; v.w += bv.w;
        }
        if (EPI == 1) {
            v.x = v.x / (1.f + __expf(-v.x));
            v.y = v.y / (1.f + __expf(-v.y));
            v.z = v.z / (1.f + __expf(-v.z));
            v.w = v.w / (1.f + __expf(-v.w));
        }
        size_t idx = (size_t)(m0 + r2) * Nout + n0 + c;
        if (C)  *(float4*)(C + idx) = v;
        if (Cr) *(uint2*)(Cr + idx) = f4_to_h4(v);
    }
}

// ---------------------------------------------------------------------------
// Residual + LayerNorm, warp-per-row, dual write.
// ---------------------------------------------------------------------------
__global__ __launch_bounds__(256)
void ln_kernel(float* __restrict__ x, const float* __restrict__ r,
               const float* __restrict__ g, const float* __restrict__ b,
               __half* __restrict__ xr)
{
    const int row  = blockIdx.x * 8 + (threadIdx.x >> 5);
    const int lane = threadIdx.x & 31;
    const size_t base = (size_t)row * 512;

    float4 v[4];
    float s = 0.f, sq = 0.f;
    #pragma unroll
    for (int u = 0; u < 4; u++) {
        float4 a = *(const float4*)(x + base + u * 128 + lane * 4);
        float4 c = *(const float4*)(r + base + u * 128 + lane * 4);
        a.x += c.x; a.y += c.y; a.z += c.z; a.w += c.w;
        v[u] = a;
        s  += (a.x + a.y) + (a.z + a.w);
        sq += (a.x * a.x + a.y * a.y) + (a.z * a.z + a.w * a.w);
    }
    #pragma unroll
    for (int m = 16; m >= 1; m >>= 1) {
        s  += __shfl_xor_sync(0xffffffffu, s,  m);
        sq += __shfl_xor_sync(0xffffffffu, sq, m);
    }
    const float mean = s * (1.f / 512.f);
    const float var  = sq * (1.f / 512.f) - mean * mean;
    const float inv  = rsqrtf(var + 1e-5f);

    #pragma unroll
    for (int u = 0; u < 4; u++) {
        float4 gv = *(const float4*)(g + u * 128 + lane * 4);
        float4 bb = *(const float4*)(b + u * 128 + lane * 4);
        float4 a = v[u];
        a.x = (a.x - mean) * inv * gv.x + bb.x;
        a.y = (a.y - mean) * inv * gv.y + bb.y;
        a.z = (a.z - mean) * inv * gv.z + bb.z;
        a.w = (a.w - mean) * inv * gv.w + bb.w;
        *(float4*)(x + base + u * 128 + lane * 4) = a;
        ((uint2*)xr)[(base + u * 128 + lane * 4) >> 2] = f4_to_h4(a);
    }
}

// ---------------------------------------------------------------------------
// Flash attention v6: round-11 structure + Q FRAGMENTS CACHED IN REGISTERS
// (loaded once per q-tile after Q is resident; S-loop avoids 4 LDSM + the
// Q-side dependency every kv tile). fp16 operands, fp32 accum/softmax,
// 2 CTA/SM, grid-stride q-tiles, one block barrier per kv tile.
// ---------------------------------------------------------------------------
#define AR 72
#define ATT3_SMEM 110592
#define ATT_GRIDX 24

__global__ __launch_bounds__(256, 2)
void attn3_kernel(const __half* __restrict__ qkv, __half* __restrict__ out)
{
    extern __shared__ __align__(1024) char smc[];
    __half* Qs    = (__half*)smc;                 // [128][72]
    __half* Ks[2] = { Qs + 128 * AR,          Qs + 128 * AR + 64 * AR };
    __half* Vs[2] = { Qs + 128 * AR + 128 * AR, Qs + 128 * AR + 192 * AR };
    __half* Ph    = Qs + 128 * AR + 256 * AR;     // [128][72]
    float*  Sf    = (float*)(smc + 73728);        // [128][72]

    const int b   = blockIdx.z;
    const int h   = blockIdx.y;
    const int off = g_offsets[b];
    const int L   = g_offsets[b + 1] - off;

    const int t    = threadIdx.x;
    const int wid  = t >> 5;
    const int lane = t & 31;

    const __half* qbase = qkv + (size_t)off * D3 + h * HDIM;
    const __half* kbase = qbase + DMODEL;
    const __half* vbase = qbase + 2 * DMODEL;

    const int kvrow = t >> 2;
    const int kvcb  = (t & 3) * 16;
    auto issueKV = [&](int j0, int s) {
        int gj = min(j0 + kvrow, L - 1);
        const __half* kp = kbase + (size_t)gj * D3 + kvcb;
        const __half* vp = vbase + (size_t)gj * D3 + kvcb;
        uint32_t dk = s2u(Ks[s] + kvrow * AR + kvcb);
        uint32_t dv = s2u(Vs[s] + kvrow * AR + kvcb);
        #pragma unroll
        for (int u = 0; u < 2; u++) {
            cp16(dk + u * 16, kp + u * 8);
            cp16(dv + u * 16, vp + u * 8);
        }
    };

    const int srow = wid * 16 + (lane >> 1);
    const int scb  = (lane & 1) * 32;
    const float* Sw = Sf + srow * AR + scb;
    __half*      Pw = Ph + srow * AR + scb;
    const int nt = (L + 63) >> 6;

    for (int qi0 = blockIdx.x * 128; qi0 < L; qi0 += ATT_GRIDX * 128) {
        __syncthreads();   // protect Qs/Ks/Vs reuse across q-tiles

        // Q load
        {
            const int qrow = t >> 1;
            const int qcb  = (t & 1) * 32;
            int gi = min(qi0 + qrow, L - 1);
            const __half* qp = qbase + (size_t)gi * D3 + qcb;
            uint32_t dst = s2u(Qs + qrow * AR + qcb);
            #pragma unroll
            for (int u = 0; u < 4; u++) cp16(dst + u * 16, qp + u * 8);
        }
        issueKV(0, 0);
        cp_commit();       // group: Q + KV0

        wmma::fragment<wmma::accumulator, 16, 16, 16, float> oacc[4];
        #pragma unroll
        for (int n = 0; n < 4; n++) wmma::fill_fragment(oacc[n], 0.f);
        float lsum = 0.f;

        // Q fragments: loaded once (after first wait), reused every kv tile
        wmma::fragment<wmma::matrix_a, 16, 16, 16, __half, wmma::row_major> qfr[4];

        for (int j = 0; j < nt; j++) {
            const int s = j & 1;
            cp_wait<0>();              // tile j (and, iter 0, Q) resident
            __syncthreads();           // orders iter j-1's reads of s^1
            if (j == 0) {
                #pragma unroll
                for (int k4 = 0; k4 < 4; k4++)
                    wmma::load_matrix_sync(qfr[k4],
                                           Qs + (wid * 16) * AR + k4 * 16, AR);
            }
            if (j + 1 < nt) { issueKV((j + 1) * 64, s ^ 1); cp_commit(); }

            // S = Qw(16x64) @ K^T(64x64), fp32 accum
            wmma::fragment<wmma::accumulator, 16, 16, 16, float> sfrag[4];
            #pragma unroll
            for (int n = 0; n < 4; n++) wmma::fill_fragment(sfrag[n], 0.f);
            #pragma unroll
            for (int k4 = 0; k4 < 4; k4++) {
                #pragma unroll
                for (int n = 0; n < 4; n++) {
                    wmma::fragment<wmma::matrix_b, 16, 16, 16, __half, wmma::col_major> bf;
                    wmma::load_matrix_sync(bf, Ks[s] + (n * 16) * AR + k4 * 16, AR);
                    wmma::mma_sync(sfrag[n], qfr[k4], bf, sfrag[n]);
                }
            }
            #pragma unroll
            for (int n = 0; n < 4; n++)
                wmma::store_matrix_sync(Sf + (wid * 16) * AR + n * 16,
                                        sfrag[n], AR, wmma::mem_row_major);
            __syncwarp();

            // warp-private softmax on own rows (no running max; scores O(1))
            {
                const int j0 = j * 64;
                float part = 0.f;
                #pragma unroll
                for (int u = 0; u < 8; u++) {
                    float4 v = *(const float4*)(Sw + u * 4);
                    int c = j0 + scb + u * 4;
                    float p0 = (c + 0 < L) ? __expf(v.x * 0.125f) : 0.f;
                    float p1 = (c + 1 < L) ? __expf(v.y * 0.125f) : 0.f;
                    float p2 = (c + 2 < L) ? __expf(v.z * 0.125f) : 0.f;
                    float p3 = (c + 3 < L) ? __expf(v.w * 0.125f) : 0.f;
                    part += (p0 + p1) + (p2 + p3);
                    v.x = p0; v.y = p1; v.z = p2; v.w = p3;
                    *(uint2*)(Pw + u * 4) = f4_to_h4(v);
                }
                lsum += part;
            }
            __syncwarp();

            // O += P(16x64) @ V(64x64)
            #pragma unroll
            for (int kk = 0; kk < 64; kk += 16) {
                wmma::fragment<wmma::matrix_a, 16, 16, 16, __half, wmma::row_major> a;
                wmma::load_matrix_sync(a, Ph + (wid * 16) * AR + kk, AR);
                #pragma unroll
                for (int n = 0; n < 4; n++) {
                    wmma::fragment<wmma::matrix_b, 16, 16, 16, __half, wmma::row_major> vf;
                    wmma::load_matrix_sync(vf, Vs[s] + kk * AR + n * 16, AR);
                    wmma::mma_sync(oacc[n], a, vf, oacc[n]);
                }
            }
        }

        // epilogue: O through Sf (warp-private rows), scale by 1/rowsum
        #pragma unroll
        for (int n = 0; n < 4; n++)
            wmma::store_matrix_sync(Sf + (wid * 16) * AR + n * 16,
                                    oacc[n], AR, wmma::mem_row_major);
        __syncwarp();

        {
            float full = lsum + __shfl_xor_sync(0xffffffffu, lsum, 1);
            float inv  = 1.f / full;
            int gi = qi0 + srow;
            if (gi < L) {
                __half* op = out + (size_t)(off + gi) * DMODEL + h * HDIM + scb;
                #pragma unroll
                for (int u = 0; u < 8; u++) {
                    float4 v = *(const float4*)(Sw + u * 4);
                    v.x *= inv; v.y *= inv; v.z *= inv; v.w *= inv;
                    *(uint2*)(op + u * 4) = f4_to_h4(v);
                }
            }
        }
        __syncwarp();
    }
}

// ---------------------------------------------------------------------------
// Launch
// ---------------------------------------------------------------------------
extern "C" void kernel_launch(void* const* d_in, const int* in_sizes, int n_in,
                              void* d_out, int out_size)
{
    const float* features   = (const float*)d_in[0];
    const int*   batch_idx  = (const int*)  d_in[1];
    const float* w_in       = (const float*)d_in[2];
    const float* w_out      = (const float*)d_in[3];
    const float* in_proj_w  = (const float*)d_in[4];
    const float* in_proj_b  = (const float*)d_in[5];
    const float* out_proj_w = (const float*)d_in[6];
    const float* out_proj_b = (const float*)d_in[7];
    const float* ln1_g      = (const float*)d_in[8];
    const float* ln1_b      = (const float*)d_in[9];
    const float* lin1_w     = (const float*)d_in[10];
    const float* lin1_b     = (const float*)d_in[11];
    const float* lin2_w     = (const float*)d_in[12];
    const float* lin2_b     = (const float*)d_in[13];
    const float* ln2_g      = (const float*)d_in[14];
    const float* ln2_b      = (const float*)d_in[15];
    (void)in_sizes; (void)n_in;

    float *xin, *x, *tmp;
    __half *xr, *featr, *qkv, *attn, *h1, *wtin, *wtout, *inw_h, *ow_h, *w1_h, *w2_h;
    cudaGetSymbolAddress((void**)&xin,   g_xin);
    cudaGetSymbolAddress((void**)&x,     g_x);
    cudaGetSymbolAddress((void**)&tmp,   g_tmp);
    cudaGetSymbolAddress((void**)&xr,    g_xr);
    cudaGetSymbolAddress((void**)&featr, g_featr);
    cudaGetSymbolAddress((void**)&qkv,   g_qkv);
    cudaGetSymbolAddress((void**)&attn,  g_attn);
    cudaGetSymbolAddress((void**)&h1,    g_h1);
    cudaGetSymbolAddress((void**)&wtin,  g_wtin);
    cudaGetSymbolAddress((void**)&wtout, g_wtout);
    cudaGetSymbolAddress((void**)&inw_h, g_inw_h);
    cudaGetSymbolAddress((void**)&ow_h,  g_ow_h);
    cudaGetSymbolAddress((void**)&w1_h,  g_w1_h);
    cudaGetSymbolAddress((void**)&w2_h,  g_w2_h);

    cudaFuncSetAttribute(attn3_kernel,
                         cudaFuncAttributeMaxDynamicSharedMemorySize, ATT3_SMEM);
    cudaFuncSetAttribute(gemm5_kernel<0>,
                         cudaFuncAttributeMaxDynamicSharedMemorySize, G5_SMEM);
    cudaFuncSetAttribute(gemm5_kernel<1>,
                         cudaFuncAttributeMaxDynamicSharedMemorySize, G5_SMEM);

    seg_kernel<<<1, 256>>>(batch_idx, N_TOK);
    prologueA<<<1536, 256>>>(w_in, w_out, features, in_proj_w);
    prologueB<<<1024, 256>>>(out_proj_w, lin1_w, lin2_w);

    const dim3 g512 (DMODEL / 128, N_TOK / 128);
    const dim3 g1536(D3 / 128,     N_TOK / 128);
    const dim3 gatt (ATT_GRIDX, NHEAD, BATCH);

    // x_in = features @ w_in   (fp32 -> xin, fp16 -> xr)
    gemm5_kernel<0><<<g512, 256, G5_SMEM>>>(featr, wtin, nullptr,
                                            xin, xr, N_TOK, DMODEL, DMODEL);
    cudaMemcpyAsync(x, xin, (size_t)N_TOK * DMODEL * sizeof(float),
                    cudaMemcpyDeviceToDevice);

    for (int l = 0; l < NLAYER; l++) {
        const __half* inw = inw_h      + (size_t)l * D3 * DMODEL;
        const float*  inb = in_proj_b  + (size_t)l * D3;
        const __half* ow  = ow_h       + (size_t)l * DMODEL * DMODEL;
        const float*  ob  = out_proj_b + (size_t)l * DMODEL;
        const __half* w1  = w1_h       + (size_t)l * DMODEL * DMODEL;
        const float*  b1  = lin1_b     + (size_t)l * DMODEL;
        const __half* w2  = w2_h       + (size_t)l * DMODEL * DMODEL;
        const float*  b2  = lin2_b     + (size_t)l * DMODEL;

        gemm5_kernel<0><<<g1536, 256, G5_SMEM>>>(xr, inw, inb,
                                                 nullptr, qkv, N_TOK, D3, DMODEL);
        attn3_kernel<<<gatt, 256, ATT3_SMEM>>>(qkv, attn);
        gemm5_kernel<0><<<g512, 256, G5_SMEM>>>(attn, ow, ob,
                                                tmp, nullptr, N_TOK, DMODEL, DMODEL);
        ln_kernel<<<N_TOK / 8, 256>>>(x, tmp, ln1_g + l * DMODEL, ln1_b + l * DMODEL, xr);
        gemm5_kernel<1><<<g512, 256, G5_SMEM>>>(xr, w1, b1,
                                                nullptr, h1, N_TOK, DMODEL, DMODEL);
        gemm5_kernel<0><<<g512, 256, G5_SMEM>>>(h1, w2, b2,
                                                tmp, nullptr, N_TOK, DMODEL, DMODEL);
        ln_kernel<<<N_TOK / 8, 256>>>(x, tmp, ln2_g + l * DMODEL, ln2_b + l * DMODEL, xr);
    }

    // out = (x + x_in) @ w_out
    addcvt_kernel<<<512, 256>>>(x, xin, featr, N_TOK * DMODEL / 4);
    gemm5_kernel<0><<<g512, 256, G5_SMEM>>>(featr, wtout, nullptr,
                                            (float*)d_out, nullptr,
                                            N_TOK, DMODEL, DMODEL);
}